// round 8
// baseline (speedup 1.0000x reference)
#include <cuda_runtime.h>
#include <math.h>

#define TT 512
#define BB 64
#define HH 256
#define KK 11
#define STARTT 9
#define STOPP 10

// ---------------- scratch (device globals: allocation-free rule) -----------
__device__ float d_XWF[(size_t)TT * BB * 1024];   // [T][B][4H] fwd input proj
__device__ float d_XWB[(size_t)TT * BB * 1024];   // [T][B][4H] bwd input proj
__device__ float d_H0[(size_t)BB * TT * 512];     // [B*T][2H] layer0 out (fwd|bwd)
__device__ float d_H1[(size_t)BB * TT * 512];     // [B*T][2H] layer1 out
__device__ float d_FEATS[(size_t)BB * TT * KK];   // [B*T][K] emissions

// ---------------- helpers --------------------------------------------------
__device__ __forceinline__ unsigned smem_u32(const void* p) {
    return (unsigned)__cvta_generic_to_shared(p);
}
__device__ __forceinline__ void st_cluster_f32(unsigned laddr, int rank, float v) {
    unsigned raddr;
    asm volatile("mapa.shared::cluster.u32 %0, %1, %2;" : "=r"(raddr) : "r"(laddr), "r"(rank));
    asm volatile("st.shared::cluster.f32 [%0], %1;" :: "r"(raddr), "f"(v) : "memory");
}
__device__ __forceinline__ void cluster_arrive() {
    asm volatile("barrier.cluster.arrive.aligned;" ::: "memory");
}
__device__ __forceinline__ void cluster_wait() {
    asm volatile("barrier.cluster.wait.aligned;" ::: "memory");
}
// fast, overflow-safe sigmoid: x->-inf gives 1/(1+inf)=0, x->+inf gives 1
__device__ __forceinline__ float fast_sigmoid(float x) {
    return __fdividef(1.f, 1.f + __expf(-x));
}
// fast tanh, clamped so e^{2x} stays finite; |err| ~2e-6
__device__ __forceinline__ float fast_tanh(float x) {
    float xc = fminf(15.f, fmaxf(-15.f, x));
    float e = __expf(2.f * xc);
    return __fdividef(e - 1.f, e + 1.f);
}

// ---------------------------------------------------------------------------
// Input projection: XW[dir][t][b][n] = x[m] . W[n][:] + bias[n]
//   layer 0: x[m] = emb[sent[m]], K=300 ; layer 1: x = d_H0 rows, K=512
// M=32768, N=1024 per dir. Tile 128x128x16, 256 thr, 8x8 micro. grid (16,256)
// Double-buffered smem, float4 global loads, one sync per k-tile.
// NOTE: no min-blocks clause — let regs float (~130) to avoid spills.
// ---------------------------------------------------------------------------
__global__ __launch_bounds__(256) void proj_kernel(
    const int* __restrict__ sent, const float* __restrict__ emb,
    const float* __restrict__ Wf, const float* __restrict__ bf,
    const float* __restrict__ Wb, const float* __restrict__ bb_,
    int K, int layer)
{
    __shared__ float As[2][16][128];
    __shared__ float Bs[2][16][128];
    __shared__ int srow[128];

    int tid = threadIdx.x;
    int bx  = blockIdx.x;          // 0..15
    int by  = blockIdx.y;          // 0..255
    int m0  = by * 128;
    int dirb = bx >> 3;
    int ncol = (bx & 7) * 128;

    const float* W    = dirb ? Wb  : Wf;
    const float* bias = dirb ? bb_ : bf;
    float*       XW   = dirb ? d_XWB : d_XWF;

    if (layer == 0 && tid < 128) srow[tid] = sent[m0 + tid];
    __syncthreads();

    int mi = tid >> 1;            // 0..127
    int ks = (tid & 1) * 8;       // 0 or 8

    const float* arow;
    if (layer == 0) arow = emb + (size_t)srow[mi] * 300;
    else            arow = d_H0 + (size_t)(m0 + mi) * 512;
    const float* wrow = W + (size_t)(ncol + mi) * K;

    int tm = tid >> 4, tn = tid & 15;

    float acc[8][8];
#pragma unroll
    for (int i = 0; i < 8; i++)
#pragma unroll
        for (int j = 0; j < 8; j++) acc[i][j] = 0.f;

    const float4 z4 = make_float4(0.f, 0.f, 0.f, 0.f);
    int nk = (K + 15) >> 4;       // number of 16-wide k-tiles

    // prefetch tile 0 into registers (K % 4 == 0 so float4 guards are per-chunk)
    float4 pa0, pa1, pb0, pb1;
    {
        int k0 = ks;
        pa0 = (k0     < K) ? *(const float4*)(arow + k0)     : z4;
        pa1 = (k0 + 4 < K) ? *(const float4*)(arow + k0 + 4) : z4;
        pb0 = (k0     < K) ? *(const float4*)(wrow + k0)     : z4;
        pb1 = (k0 + 4 < K) ? *(const float4*)(wrow + k0 + 4) : z4;
    }
    As[0][ks + 0][mi] = pa0.x; As[0][ks + 1][mi] = pa0.y;
    As[0][ks + 2][mi] = pa0.z; As[0][ks + 3][mi] = pa0.w;
    As[0][ks + 4][mi] = pa1.x; As[0][ks + 5][mi] = pa1.y;
    As[0][ks + 6][mi] = pa1.z; As[0][ks + 7][mi] = pa1.w;
    Bs[0][ks + 0][mi] = pb0.x; Bs[0][ks + 1][mi] = pb0.y;
    Bs[0][ks + 2][mi] = pb0.z; Bs[0][ks + 3][mi] = pb0.w;
    Bs[0][ks + 4][mi] = pb1.x; Bs[0][ks + 5][mi] = pb1.y;
    Bs[0][ks + 6][mi] = pb1.z; Bs[0][ks + 7][mi] = pb1.w;
    __syncthreads();

    for (int it = 0; it < nk; ++it) {
        int cur = it & 1;

        // prefetch next tile into registers (overlaps with compute below)
        if (it + 1 < nk) {
            int k0 = (it + 1) * 16 + ks;
            pa0 = (k0     < K) ? *(const float4*)(arow + k0)     : z4;
            pa1 = (k0 + 4 < K) ? *(const float4*)(arow + k0 + 4) : z4;
            pb0 = (k0     < K) ? *(const float4*)(wrow + k0)     : z4;
            pb1 = (k0 + 4 < K) ? *(const float4*)(wrow + k0 + 4) : z4;
        }

        const float (*Ac)[128] = As[cur];
        const float (*Bc)[128] = Bs[cur];
#pragma unroll
        for (int k = 0; k < 16; k++) {
            float4 a0 = *(const float4*)&Ac[k][tm * 4];
            float4 a1 = *(const float4*)&Ac[k][64 + tm * 4];
            float4 b0 = *(const float4*)&Bc[k][tn * 4];
            float4 b1 = *(const float4*)&Bc[k][64 + tn * 4];
            float a[8] = {a0.x, a0.y, a0.z, a0.w, a1.x, a1.y, a1.z, a1.w};
            float b[8] = {b0.x, b0.y, b0.z, b0.w, b1.x, b1.y, b1.z, b1.w};
#pragma unroll
            for (int i = 0; i < 8; i++)
#pragma unroll
                for (int j = 0; j < 8; j++)
                    acc[i][j] = fmaf(a[i], b[j], acc[i][j]);
        }

        if (it + 1 < nk) {
            int nb = cur ^ 1;
            As[nb][ks + 0][mi] = pa0.x; As[nb][ks + 1][mi] = pa0.y;
            As[nb][ks + 2][mi] = pa0.z; As[nb][ks + 3][mi] = pa0.w;
            As[nb][ks + 4][mi] = pa1.x; As[nb][ks + 5][mi] = pa1.y;
            As[nb][ks + 6][mi] = pa1.z; As[nb][ks + 7][mi] = pa1.w;
            Bs[nb][ks + 0][mi] = pb0.x; Bs[nb][ks + 1][mi] = pb0.y;
            Bs[nb][ks + 2][mi] = pb0.z; Bs[nb][ks + 3][mi] = pb0.w;
            Bs[nb][ks + 4][mi] = pb1.x; Bs[nb][ks + 5][mi] = pb1.y;
            Bs[nb][ks + 6][mi] = pb1.z; Bs[nb][ks + 7][mi] = pb1.w;
            __syncthreads();
        }
    }

    // epilogue: vectorized, coalesced stores with bias
    float4 ba  = *(const float4*)&bias[ncol + tn * 4];
    float4 bb2 = *(const float4*)&bias[ncol + 64 + tn * 4];
#pragma unroll
    for (int i = 0; i < 8; i++) {
        int mm = m0 + ((i < 4) ? (tm * 4 + i) : (64 + tm * 4 + (i - 4)));
        int b_ = mm >> 9, t_ = mm & 511;          // m = b*512 + t
        float* orow = XW + ((size_t)t_ * 64 + b_) * 1024 + ncol;
        float4 o1 = make_float4(acc[i][0] + ba.x,  acc[i][1] + ba.y,
                                acc[i][2] + ba.z,  acc[i][3] + ba.w);
        float4 o2 = make_float4(acc[i][4] + bb2.x, acc[i][5] + bb2.y,
                                acc[i][6] + bb2.z, acc[i][7] + bb2.w);
        *(float4*)(orow + tn * 4)      = o1;
        *(float4*)(orow + 64 + tn * 4) = o2;
    }
}

// ---------------------------------------------------------------------------
// Recurrent LSTM. grid=128 CTAs, cluster 8, 256 thr. Cluster=(dir, 8 batches).
// CTA s owns h cols [s*32, s*32+32). W_hh slice in registers (128 f/thread).
// h exchanged via multicast st.shared::cluster, double-buffered.
// One split cluster barrier per step (arrive; global store + prefetch; wait).
// ---------------------------------------------------------------------------
__global__ __launch_bounds__(256) __cluster_dims__(8, 1, 1)
void rec_kernel(const float* __restrict__ whhF, const float* __restrict__ whhB, int outSel)
{
    __shared__ float hsm[2][8][288];   // [buf][batch][k padded: k + (k>>5)*4]

    int cta = blockIdx.x;
    int s   = cta & 7;
    int cl  = cta >> 3;
    int dir = cl >> 3;      // 0 fwd, 1 bwd
    int bg  = cl & 7;

    const float* XW   = dir ? d_XWB : d_XWF;
    const float* Whh  = dir ? whhB  : whhF;
    float*       Hout = outSel ? d_H1 : d_H0;

    int tid  = threadIdx.x;
    int w    = tid >> 5, lane = tid & 31;
    int jsub = lane >> 3, kr = lane & 7;
    int jl   = w * 4 + jsub;
    int jg   = s * 32 + jl;
    int b    = kr;
    int bglob = bg * 8 + b;

    // W_hh slice: Wreg[g][q] = W[g*256+jg][kr*32 + q*4 .. +3]
    float4 Wreg[4][8];
#pragma unroll
    for (int g = 0; g < 4; g++) {
        const float* wr = Whh + (size_t)(g * 256 + jg) * 256 + kr * 32;
#pragma unroll
        for (int q = 0; q < 8; q++) Wreg[g][q] = *(const float4*)(wr + q * 4);
    }

    for (int i = tid; i < 2 * 8 * 288; i += 256) (&hsm[0][0][0])[i] = 0.f;
    float c = 0.f;
    __syncthreads();
    cluster_arrive();

    // prefetch xw for step 0 (overlaps barrier wait)
    int t0 = dir ? 511 : 0;
    const float* xwp = XW + ((size_t)t0 * 64 + bglob) * 1024 + jg;
    float xw0 = xwp[0], xw1 = xwp[256], xw2 = xwp[512], xw3 = xwp[768];

    cluster_wait();                    // zeros + peers ready

    int buf = 0;
    for (int step = 0; step < 512; ++step) {
        int t = dir ? (511 - step) : step;

        float acc[4][8];
#pragma unroll
        for (int g = 0; g < 4; g++)
#pragma unroll
            for (int q = 0; q < 8; q++) acc[g][q] = 0.f;

        const float* hb = &hsm[buf][0][0];
#pragma unroll
        for (int q = 0; q < 8; q++) {
#pragma unroll
            for (int bb2 = 0; bb2 < 8; bb2++) {
                float4 hv = *(const float4*)(hb + bb2 * 288 + kr * 36 + q * 4);
#pragma unroll
                for (int g = 0; g < 4; g++) {
                    acc[g][bb2] = fmaf(Wreg[g][q].x, hv.x, acc[g][bb2]);
                    acc[g][bb2] = fmaf(Wreg[g][q].y, hv.y, acc[g][bb2]);
                    acc[g][bb2] = fmaf(Wreg[g][q].z, hv.z, acc[g][bb2]);
                    acc[g][bb2] = fmaf(Wreg[g][q].w, hv.w, acc[g][bb2]);
                }
            }
        }

        // paired butterfly reduction over the 8 kr lanes:
        // after 3 levels, lane kr holds the full sum for batch b=kr.
        bool hi  = (kr & 4) != 0;
        bool md  = (kr & 2) != 0;
        bool lo  = (kr & 1) != 0;
        float gate[4];
#pragma unroll
        for (int g = 0; g < 4; g++) {
            float t4[4];
#pragma unroll
            for (int b2 = 0; b2 < 4; b2++) {
                float keep = hi ? acc[g][b2 + 4] : acc[g][b2];
                float send = hi ? acc[g][b2]     : acc[g][b2 + 4];
                t4[b2] = keep + __shfl_xor_sync(0xffffffffu, send, 4);
            }
            float t2[2];
#pragma unroll
            for (int b2 = 0; b2 < 2; b2++) {
                float keep = md ? t4[b2 + 2] : t4[b2];
                float send = md ? t4[b2]     : t4[b2 + 2];
                t2[b2] = keep + __shfl_xor_sync(0xffffffffu, send, 2);
            }
            {
                float keep = lo ? t2[1] : t2[0];
                float send = lo ? t2[0] : t2[1];
                gate[g] = keep + __shfl_xor_sync(0xffffffffu, send, 1);
            }
        }

        float gi = gate[0] + xw0;
        float gf = gate[1] + xw1;
        float gc = gate[2] + xw2;
        float go = gate[3] + xw3;
        float i_ = fast_sigmoid(gi);
        float f_ = fast_sigmoid(gf);
        float g_ = fast_tanh(gc);
        float o_ = fast_sigmoid(go);
        c = fmaf(f_, c, i_ * g_);
        float h = o_ * fast_tanh(c);

        // multicast h into next buffer of all 8 cluster CTAs (padded index)
        unsigned laddr = smem_u32(&hsm[buf ^ 1][b][jg + s * 4]);
#pragma unroll
        for (int r = 0; r < 8; r++) st_cluster_f32(laddr, r, h);

        cluster_arrive();

        // overlapped with barrier: persist h, prefetch next xw
        Hout[((size_t)bglob * 512 + t) * 512 + dir * 256 + jg] = h;
        if (step + 1 < 512) {
            int tn_ = dir ? (511 - (step + 1)) : (step + 1);
            const float* xq = XW + ((size_t)tn_ * 64 + bglob) * 1024 + jg;
            xw0 = xq[0]; xw1 = xq[256]; xw2 = xq[512]; xw3 = xq[768];
        }

        cluster_wait();
        buf ^= 1;
    }
}

// ---------------------------------------------------------------------------
// Emissions: FEATS[m][n] = H1[m][:512] . fc_w[n][:] + fc_b[n]. Warp per row.
// ---------------------------------------------------------------------------
__global__ __launch_bounds__(256) void feats_kernel(
    const float* __restrict__ fcw, const float* __restrict__ fcb)
{
    __shared__ float wsm[KK * 512];
    int tid = threadIdx.x;
    for (int i = tid; i < KK * 512; i += 256) wsm[i] = fcw[i];
    __syncthreads();

    int warp = tid >> 5, lane = tid & 31;
    size_t row = (size_t)blockIdx.x * 8 + warp;
    const float* hr = d_H1 + row * 512;

    float hreg[16];
#pragma unroll
    for (int i = 0; i < 16; i++) hreg[i] = hr[lane + 32 * i];

#pragma unroll
    for (int n = 0; n < KK; n++) {
        float p = 0.f;
#pragma unroll
        for (int i = 0; i < 16; i++) p = fmaf(hreg[i], wsm[n * 512 + lane + 32 * i], p);
        p += __shfl_xor_sync(0xffffffffu, p, 16);
        p += __shfl_xor_sync(0xffffffffu, p, 8);
        p += __shfl_xor_sync(0xffffffffu, p, 4);
        p += __shfl_xor_sync(0xffffffffu, p, 2);
        p += __shfl_xor_sync(0xffffffffu, p, 1);
        if (lane == 0) d_FEATS[row * KK + n] = p + __ldg(&fcb[n]);
    }
}

// ---------------------------------------------------------------------------
// Viterbi, one warp per batch. fv in lanes (lane=tag). Strict '>' = first-max
// matching jnp.argmax. mode 0: out=[score(64)|path(64*512)]; 1: path; 2: score
// ---------------------------------------------------------------------------
__global__ __launch_bounds__(32) void viterbi_kernel(
    const float* __restrict__ trans, float* __restrict__ out, int mode)
{
    __shared__ unsigned char bp[512][16];
    int b = blockIdx.x, lane = threadIdx.x;
    int li = (lane < KK) ? lane : (KK - 1);

    float tr[KK];
#pragma unroll
    for (int p = 0; p < KK; p++) tr[p] = trans[li * KK + p];   // trans[next=li][prev=p]
    float trStop = trans[STOPP * KK + li];

    float fv = (lane < KK) ? ((lane == STARTT) ? 0.f : -1000.f) : -3.0e38f;
    const float* fb = d_FEATS + (size_t)b * 512 * KK;

    for (int t = 0; t < 512; t++) {
        float best = -3.0e38f; int bi = 0;
#pragma unroll
        for (int p = 0; p < KK; p++) {
            float fp = __shfl_sync(0xffffffffu, fv, p);
            float sc = fp + tr[p];
            if (sc > best) { best = sc; bi = p; }
        }
        if (lane < KK) bp[t][lane] = (unsigned char)bi;
        float ft = fb[t * KK + li];
        float nfv = best + ft;
        fv = (lane < KK) ? nfv : -3.0e38f;
    }
    __syncwarp();

    float term = (lane < KK) ? (fv + trStop) : -3.0e38f;
    float best = -3.0e38f; int bt = 0;
#pragma unroll
    for (int p = 0; p < KK; p++) {
        float v = __shfl_sync(0xffffffffu, term, p);
        if (v > best) { best = v; bt = p; }
    }
    __syncwarp();

    if (lane == 0) {
        float* scoreOut = nullptr; float* pathOut = nullptr;
        if (mode == 0)      { scoreOut = out; pathOut = out + 64; }
        else if (mode == 1) { pathOut = out; }
        else                { scoreOut = out; }
        if (scoreOut) scoreOut[b] = best;
        if (pathOut) {
            int tag = bt;
            pathOut[(size_t)b * 512 + 511] = (float)tag;
            for (int t = 511; t >= 1; t--) {
                tag = bp[t][tag];
                pathOut[(size_t)b * 512 + (t - 1)] = (float)tag;
            }
        }
    }
}

// ---------------------------------------------------------------------------
extern "C" void kernel_launch(void* const* d_in, const int* in_sizes, int n_in,
                              void* d_out, int out_size)
{
    const int*   sent  = (const int*)d_in[0];
    // d_in[1] = batch_lengths (all == T; unused)
    const float* emb   = (const float*)d_in[2];
    const float* fcw   = (const float*)d_in[3];
    const float* fcb   = (const float*)d_in[4];
    const float* trans = (const float*)d_in[5];
    const float* wih0f = (const float*)d_in[6];
    const float* whh0f = (const float*)d_in[7];
    const float* b0f   = (const float*)d_in[8];
    const float* wih0b = (const float*)d_in[9];
    const float* whh0b = (const float*)d_in[10];
    const float* b0b   = (const float*)d_in[11];
    const float* wih1f = (const float*)d_in[12];
    const float* whh1f = (const float*)d_in[13];
    const float* b1f   = (const float*)d_in[14];
    const float* wih1b = (const float*)d_in[15];
    const float* whh1b = (const float*)d_in[16];
    const float* b1b   = (const float*)d_in[17];
    float* out = (float*)d_out;

    int mode = 0;
    if (out_size == 64 * 512) mode = 1;         // path only
    else if (out_size == 64) mode = 2;          // score only
    // default: [score(64) | path(64*512)]

    dim3 pgrid(16, 256);
    proj_kernel<<<pgrid, 256>>>(sent, emb, wih0f, b0f, wih0b, b0b, 300, 0);
    rec_kernel<<<128, 256>>>(whh0f, whh0b, 0);
    proj_kernel<<<pgrid, 256>>>(sent, emb, wih1f, b1f, wih1b, b1b, 512, 1);
    rec_kernel<<<128, 256>>>(whh1f, whh1b, 1);
    feats_kernel<<<4096, 256>>>(fcw, fcb);
    viterbi_kernel<<<64, 32>>>(trans, out, mode);
}

// round 10
// speedup vs baseline: 1.2611x; 1.2611x over previous
#include <cuda_runtime.h>
#include <math.h>

#define TT 512
#define BB 64
#define HH 256
#define KK 11
#define STARTT 9
#define STOPP 10

typedef unsigned long long u64;

// ---------------- scratch (device globals: allocation-free rule) -----------
__device__ float d_XWF[(size_t)TT * BB * 1024];   // [T][B][4H] fwd input proj
__device__ float d_XWB[(size_t)TT * BB * 1024];   // [T][B][4H] bwd input proj
__device__ float d_H0[(size_t)BB * TT * 512];     // [B*T][2H] layer0 out (fwd|bwd)
__device__ float d_H1[(size_t)BB * TT * 512];     // [B*T][2H] layer1 out
__device__ float d_FEATS[(size_t)BB * TT * KK];   // [B*T][K] emissions

// ---------------- helpers --------------------------------------------------
__device__ __forceinline__ unsigned smem_u32(const void* p) {
    return (unsigned)__cvta_generic_to_shared(p);
}
__device__ __forceinline__ void st_cluster_f32(unsigned laddr, int rank, float v) {
    unsigned raddr;
    asm volatile("mapa.shared::cluster.u32 %0, %1, %2;" : "=r"(raddr) : "r"(laddr), "r"(rank));
    asm volatile("st.shared::cluster.f32 [%0], %1;" :: "r"(raddr), "f"(v) : "memory");
}
__device__ __forceinline__ void cluster_arrive() {
    asm volatile("barrier.cluster.arrive.aligned;" ::: "memory");
}
__device__ __forceinline__ void cluster_wait() {
    asm volatile("barrier.cluster.wait.aligned;" ::: "memory");
}
__device__ __forceinline__ float fast_sigmoid(float x) {
    return __fdividef(1.f, 1.f + __expf(-x));
}
__device__ __forceinline__ float fast_tanh(float x) {
    float xc = fminf(15.f, fmaxf(-15.f, x));
    float e = __expf(2.f * xc);
    return __fdividef(e - 1.f, e + 1.f);
}

// ---- packed fp32x2 (Blackwell FFMA2) --------------------------------------
__device__ __forceinline__ u64 pack2(float lo, float hi) {
    u64 r; asm("mov.b64 %0, {%1, %2};" : "=l"(r) : "f"(lo), "f"(hi)); return r;
}
__device__ __forceinline__ float2 unpack2(u64 v) {
    float2 f; asm("mov.b64 {%0, %1}, %2;" : "=f"(f.x), "=f"(f.y) : "l"(v)); return f;
}
__device__ __forceinline__ void fma2(u64& d, u64 a, u64 b) {
    asm("fma.rn.f32x2 %0, %1, %2, %0;" : "+l"(d) : "l"(a), "l"(b));
}
__device__ __forceinline__ u64 add2(u64 a, u64 b) {
    u64 r; asm("add.rn.f32x2 %0, %1, %2;" : "=l"(r) : "l"(a), "l"(b)); return r;
}

// ---------------------------------------------------------------------------
// Input projection: XW[dir][t][b][n] = x[m] . W[n][:] + bias[n]
// Packed f32x2 accumulators: acc[i][jp] holds columns (2jp, 2jp+1).
// ---------------------------------------------------------------------------
__global__ __launch_bounds__(256) void proj_kernel(
    const int* __restrict__ sent, const float* __restrict__ emb,
    const float* __restrict__ Wf, const float* __restrict__ bf,
    const float* __restrict__ Wb, const float* __restrict__ bb_,
    int K, int layer)
{
    __shared__ float As[2][16][128];
    __shared__ float Bs[2][16][128];
    __shared__ int srow[128];

    int tid = threadIdx.x;
    int bx  = blockIdx.x;          // 0..15
    int by  = blockIdx.y;          // 0..255
    int m0  = by * 128;
    int dirb = bx >> 3;
    int ncol = (bx & 7) * 128;

    const float* W    = dirb ? Wb  : Wf;
    const float* bias = dirb ? bb_ : bf;
    float*       XW   = dirb ? d_XWB : d_XWF;

    if (layer == 0 && tid < 128) srow[tid] = sent[m0 + tid];
    __syncthreads();

    int mi = tid >> 1;            // 0..127
    int ks = (tid & 1) * 8;       // 0 or 8

    const float* arow;
    if (layer == 0) arow = emb + (size_t)srow[mi] * 300;
    else            arow = d_H0 + (size_t)(m0 + mi) * 512;
    const float* wrow = W + (size_t)(ncol + mi) * K;

    int tm = tid >> 4, tn = tid & 15;

    u64 accp[8][4];
#pragma unroll
    for (int i = 0; i < 8; i++)
#pragma unroll
        for (int j = 0; j < 4; j++) accp[i][j] = 0ull;

    const float4 z4 = make_float4(0.f, 0.f, 0.f, 0.f);
    int nk = (K + 15) >> 4;

    float4 pa0, pa1, pb0, pb1;
    {
        int k0 = ks;
        pa0 = (k0     < K) ? *(const float4*)(arow + k0)     : z4;
        pa1 = (k0 + 4 < K) ? *(const float4*)(arow + k0 + 4) : z4;
        pb0 = (k0     < K) ? *(const float4*)(wrow + k0)     : z4;
        pb1 = (k0 + 4 < K) ? *(const float4*)(wrow + k0 + 4) : z4;
    }
    As[0][ks + 0][mi] = pa0.x; As[0][ks + 1][mi] = pa0.y;
    As[0][ks + 2][mi] = pa0.z; As[0][ks + 3][mi] = pa0.w;
    As[0][ks + 4][mi] = pa1.x; As[0][ks + 5][mi] = pa1.y;
    As[0][ks + 6][mi] = pa1.z; As[0][ks + 7][mi] = pa1.w;
    Bs[0][ks + 0][mi] = pb0.x; Bs[0][ks + 1][mi] = pb0.y;
    Bs[0][ks + 2][mi] = pb0.z; Bs[0][ks + 3][mi] = pb0.w;
    Bs[0][ks + 4][mi] = pb1.x; Bs[0][ks + 5][mi] = pb1.y;
    Bs[0][ks + 6][mi] = pb1.z; Bs[0][ks + 7][mi] = pb1.w;
    __syncthreads();

    for (int it = 0; it < nk; ++it) {
        int cur = it & 1;

        if (it + 1 < nk) {
            int k0 = (it + 1) * 16 + ks;
            pa0 = (k0     < K) ? *(const float4*)(arow + k0)     : z4;
            pa1 = (k0 + 4 < K) ? *(const float4*)(arow + k0 + 4) : z4;
            pb0 = (k0     < K) ? *(const float4*)(wrow + k0)     : z4;
            pb1 = (k0 + 4 < K) ? *(const float4*)(wrow + k0 + 4) : z4;
        }

        const float (*Ac)[128] = As[cur];
        const float (*Bc)[128] = Bs[cur];
#pragma unroll
        for (int k = 0; k < 16; k++) {
            float4 a0 = *(const float4*)&Ac[k][tm * 4];
            float4 a1 = *(const float4*)&Ac[k][64 + tm * 4];
            float4 b0 = *(const float4*)&Bc[k][tn * 4];
            float4 b1 = *(const float4*)&Bc[k][64 + tn * 4];
            u64 bp0 = pack2(b0.x, b0.y), bp1 = pack2(b0.z, b0.w);
            u64 bp2 = pack2(b1.x, b1.y), bp3 = pack2(b1.z, b1.w);
            float a[8] = {a0.x, a0.y, a0.z, a0.w, a1.x, a1.y, a1.z, a1.w};
#pragma unroll
            for (int i = 0; i < 8; i++) {
                u64 ad = pack2(a[i], a[i]);
                fma2(accp[i][0], ad, bp0);
                fma2(accp[i][1], ad, bp1);
                fma2(accp[i][2], ad, bp2);
                fma2(accp[i][3], ad, bp3);
            }
        }

        if (it + 1 < nk) {
            int nb = cur ^ 1;
            As[nb][ks + 0][mi] = pa0.x; As[nb][ks + 1][mi] = pa0.y;
            As[nb][ks + 2][mi] = pa0.z; As[nb][ks + 3][mi] = pa0.w;
            As[nb][ks + 4][mi] = pa1.x; As[nb][ks + 5][mi] = pa1.y;
            As[nb][ks + 6][mi] = pa1.z; As[nb][ks + 7][mi] = pa1.w;
            Bs[nb][ks + 0][mi] = pb0.x; Bs[nb][ks + 1][mi] = pb0.y;
            Bs[nb][ks + 2][mi] = pb0.z; Bs[nb][ks + 3][mi] = pb0.w;
            Bs[nb][ks + 4][mi] = pb1.x; Bs[nb][ks + 5][mi] = pb1.y;
            Bs[nb][ks + 6][mi] = pb1.z; Bs[nb][ks + 7][mi] = pb1.w;
            __syncthreads();
        }
    }

    // epilogue: unpack pairs, add bias, coalesced float4 stores
    float4 ba  = *(const float4*)&bias[ncol + tn * 4];
    float4 bb2 = *(const float4*)&bias[ncol + 64 + tn * 4];
#pragma unroll
    for (int i = 0; i < 8; i++) {
        int mm = m0 + ((i < 4) ? (tm * 4 + i) : (64 + tm * 4 + (i - 4)));
        int b_ = mm >> 9, t_ = mm & 511;          // m = b*512 + t
        float* orow = XW + ((size_t)t_ * 64 + b_) * 1024 + ncol;
        float2 p0 = unpack2(accp[i][0]);
        float2 p1 = unpack2(accp[i][1]);
        float2 p2 = unpack2(accp[i][2]);
        float2 p3 = unpack2(accp[i][3]);
        float4 o1 = make_float4(p0.x + ba.x,  p0.y + ba.y,  p1.x + ba.z,  p1.y + ba.w);
        float4 o2 = make_float4(p2.x + bb2.x, p2.y + bb2.y, p3.x + bb2.z, p3.y + bb2.w);
        *(float4*)(orow + tn * 4)      = o1;
        *(float4*)(orow + 64 + tn * 4) = o2;
    }
}

// ---------------------------------------------------------------------------
// Recurrent LSTM. grid=128 CTAs, cluster 8, 256 thr. Cluster=(dir, 8 batches).
// W_hh slice packed along gate pairs: Wp[p][q][c] = (W[2p], W[2p+1]) at k =
// kr*32+q*4+c. Gate GEMM via FFMA2; each h-component duplicated once, reused
// by both gate-pair accumulators. Reduction on packed 64-bit with add.f32x2.
// ---------------------------------------------------------------------------
__global__ __launch_bounds__(256) __cluster_dims__(8, 1, 1)
void rec_kernel(const float* __restrict__ whhF, const float* __restrict__ whhB, int outSel)
{
    __shared__ float hsm[2][8][288];   // [buf][batch][k padded: k + (k>>5)*4]

    int cta = blockIdx.x;
    int s   = cta & 7;
    int cl  = cta >> 3;
    int dir = cl >> 3;      // 0 fwd, 1 bwd
    int bg  = cl & 7;

    const float* XW   = dir ? d_XWB : d_XWF;
    const float* Whh  = dir ? whhB  : whhF;
    float*       Hout = outSel ? d_H1 : d_H0;

    int tid  = threadIdx.x;
    int w    = tid >> 5, lane = tid & 31;
    int jsub = lane >> 3, kr = lane & 7;
    int jl   = w * 4 + jsub;
    int jg   = s * 32 + jl;
    int b    = kr;
    int bglob = bg * 8 + b;

    // load 4 gate rows' k-slices, pack along gate pairs
    u64 Wp[2][8][4];
    {
        const float* w0 = Whh + (size_t)(0 * 256 + jg) * 256 + kr * 32;
        const float* w1 = Whh + (size_t)(1 * 256 + jg) * 256 + kr * 32;
        const float* w2 = Whh + (size_t)(2 * 256 + jg) * 256 + kr * 32;
        const float* w3 = Whh + (size_t)(3 * 256 + jg) * 256 + kr * 32;
#pragma unroll
        for (int q = 0; q < 8; q++) {
            float4 a = *(const float4*)(w0 + q * 4);
            float4 bq = *(const float4*)(w1 + q * 4);
            float4 cq = *(const float4*)(w2 + q * 4);
            float4 dq = *(const float4*)(w3 + q * 4);
            Wp[0][q][0] = pack2(a.x, bq.x); Wp[0][q][1] = pack2(a.y, bq.y);
            Wp[0][q][2] = pack2(a.z, bq.z); Wp[0][q][3] = pack2(a.w, bq.w);
            Wp[1][q][0] = pack2(cq.x, dq.x); Wp[1][q][1] = pack2(cq.y, dq.y);
            Wp[1][q][2] = pack2(cq.z, dq.z); Wp[1][q][3] = pack2(cq.w, dq.w);
        }
    }

    for (int i = tid; i < 2 * 8 * 288; i += 256) (&hsm[0][0][0])[i] = 0.f;
    float c = 0.f;
    __syncthreads();
    cluster_arrive();

    // prefetch xw for step 0 (overlaps barrier wait)
    int t0 = dir ? 511 : 0;
    const float* xwp = XW + ((size_t)t0 * 64 + bglob) * 1024 + jg;
    float xw0 = xwp[0], xw1 = xwp[256], xw2 = xwp[512], xw3 = xwp[768];

    cluster_wait();                    // zeros + peers ready

    int buf = 0;
    for (int step = 0; step < 512; ++step) {
        int t = dir ? (511 - step) : step;

        u64 accP[2][8];
#pragma unroll
        for (int p = 0; p < 2; p++)
#pragma unroll
            for (int q = 0; q < 8; q++) accP[p][q] = 0ull;

        const float* hb = &hsm[buf][0][0];
#pragma unroll
        for (int q = 0; q < 8; q++) {
#pragma unroll
            for (int bb2 = 0; bb2 < 8; bb2++) {
                float4 hv = *(const float4*)(hb + bb2 * 288 + kr * 36 + q * 4);
                u64 hx = pack2(hv.x, hv.x);
                u64 hy = pack2(hv.y, hv.y);
                u64 hz = pack2(hv.z, hv.z);
                u64 hw = pack2(hv.w, hv.w);
                fma2(accP[0][bb2], Wp[0][q][0], hx);
                fma2(accP[1][bb2], Wp[1][q][0], hx);
                fma2(accP[0][bb2], Wp[0][q][1], hy);
                fma2(accP[1][bb2], Wp[1][q][1], hy);
                fma2(accP[0][bb2], Wp[0][q][2], hz);
                fma2(accP[1][bb2], Wp[1][q][2], hz);
                fma2(accP[0][bb2], Wp[0][q][3], hw);
                fma2(accP[1][bb2], Wp[1][q][3], hw);
            }
        }

        // paired butterfly reduction over the 8 kr lanes (packed 64-bit adds)
        bool hi  = (kr & 4) != 0;
        bool md  = (kr & 2) != 0;
        bool lo  = (kr & 1) != 0;
        u64 gatep[2];
#pragma unroll
        for (int p = 0; p < 2; p++) {
            u64 t4[4];
#pragma unroll
            for (int b2 = 0; b2 < 4; b2++) {
                u64 keep = hi ? accP[p][b2 + 4] : accP[p][b2];
                u64 send = hi ? accP[p][b2]     : accP[p][b2 + 4];
                t4[b2] = add2(keep, __shfl_xor_sync(0xffffffffu, send, 4));
            }
            u64 t2[2];
#pragma unroll
            for (int b2 = 0; b2 < 2; b2++) {
                u64 keep = md ? t4[b2 + 2] : t4[b2];
                u64 send = md ? t4[b2]     : t4[b2 + 2];
                t2[b2] = add2(keep, __shfl_xor_sync(0xffffffffu, send, 2));
            }
            {
                u64 keep = lo ? t2[1] : t2[0];
                u64 send = lo ? t2[0] : t2[1];
                gatep[p] = add2(keep, __shfl_xor_sync(0xffffffffu, send, 1));
            }
        }

        float2 g01 = unpack2(gatep[0]);   // (i, f)
        float2 g23 = unpack2(gatep[1]);   // (g, o)
        float gi = g01.x + xw0;
        float gf = g01.y + xw1;
        float gc = g23.x + xw2;
        float go = g23.y + xw3;
        float i_ = fast_sigmoid(gi);
        float f_ = fast_sigmoid(gf);
        float g_ = fast_tanh(gc);
        float o_ = fast_sigmoid(go);
        c = fmaf(f_, c, i_ * g_);
        float h = o_ * fast_tanh(c);

        // multicast h into next buffer of all 8 cluster CTAs (padded index)
        unsigned laddr = smem_u32(&hsm[buf ^ 1][b][jg + s * 4]);
#pragma unroll
        for (int r = 0; r < 8; r++) st_cluster_f32(laddr, r, h);

        cluster_arrive();

        // overlapped with barrier: persist h, prefetch next xw
        Hout[((size_t)bglob * 512 + t) * 512 + dir * 256 + jg] = h;
        if (step + 1 < 512) {
            int tn_ = dir ? (511 - (step + 1)) : (step + 1);
            const float* xq = XW + ((size_t)tn_ * 64 + bglob) * 1024 + jg;
            xw0 = xq[0]; xw1 = xq[256]; xw2 = xq[512]; xw3 = xq[768];
        }

        cluster_wait();
        buf ^= 1;
    }
}

// ---------------------------------------------------------------------------
// Emissions: FEATS[m][n] = H1[m][:512] . fc_w[n][:] + fc_b[n]. Warp per row.
// ---------------------------------------------------------------------------
__global__ __launch_bounds__(256) void feats_kernel(
    const float* __restrict__ fcw, const float* __restrict__ fcb)
{
    __shared__ float wsm[KK * 512];
    int tid = threadIdx.x;
    for (int i = tid; i < KK * 512; i += 256) wsm[i] = fcw[i];
    __syncthreads();

    int warp = tid >> 5, lane = tid & 31;
    size_t row = (size_t)blockIdx.x * 8 + warp;
    const float* hr = d_H1 + row * 512;

    float hreg[16];
#pragma unroll
    for (int i = 0; i < 16; i++) hreg[i] = hr[lane + 32 * i];

#pragma unroll
    for (int n = 0; n < KK; n++) {
        float p = 0.f;
#pragma unroll
        for (int i = 0; i < 16; i++) p = fmaf(hreg[i], wsm[n * 512 + lane + 32 * i], p);
        p += __shfl_xor_sync(0xffffffffu, p, 16);
        p += __shfl_xor_sync(0xffffffffu, p, 8);
        p += __shfl_xor_sync(0xffffffffu, p, 4);
        p += __shfl_xor_sync(0xffffffffu, p, 2);
        p += __shfl_xor_sync(0xffffffffu, p, 1);
        if (lane == 0) d_FEATS[row * KK + n] = p + __ldg(&fcb[n]);
    }
}

// ---------------------------------------------------------------------------
// Viterbi, one warp per batch. fv in lanes (lane=tag). Strict '>' = first-max
// matching jnp.argmax. mode 0: out=[score(64)|path(64*512)]; 1: path; 2: score
// ---------------------------------------------------------------------------
__global__ __launch_bounds__(32) void viterbi_kernel(
    const float* __restrict__ trans, float* __restrict__ out, int mode)
{
    __shared__ unsigned char bp[512][16];
    int b = blockIdx.x, lane = threadIdx.x;
    int li = (lane < KK) ? lane : (KK - 1);

    float tr[KK];
#pragma unroll
    for (int p = 0; p < KK; p++) tr[p] = trans[li * KK + p];   // trans[next=li][prev=p]
    float trStop = trans[STOPP * KK + li];

    float fv = (lane < KK) ? ((lane == STARTT) ? 0.f : -1000.f) : -3.0e38f;
    const float* fb = d_FEATS + (size_t)b * 512 * KK;

    for (int t = 0; t < 512; t++) {
        float best = -3.0e38f; int bi = 0;
#pragma unroll
        for (int p = 0; p < KK; p++) {
            float fp = __shfl_sync(0xffffffffu, fv, p);
            float sc = fp + tr[p];
            if (sc > best) { best = sc; bi = p; }
        }
        if (lane < KK) bp[t][lane] = (unsigned char)bi;
        float ft = fb[t * KK + li];
        float nfv = best + ft;
        fv = (lane < KK) ? nfv : -3.0e38f;
    }
    __syncwarp();

    float term = (lane < KK) ? (fv + trStop) : -3.0e38f;
    float best = -3.0e38f; int bt = 0;
#pragma unroll
    for (int p = 0; p < KK; p++) {
        float v = __shfl_sync(0xffffffffu, term, p);
        if (v > best) { best = v; bt = p; }
    }
    __syncwarp();

    if (lane == 0) {
        float* scoreOut = nullptr; float* pathOut = nullptr;
        if (mode == 0)      { scoreOut = out; pathOut = out + 64; }
        else if (mode == 1) { pathOut = out; }
        else                { scoreOut = out; }
        if (scoreOut) scoreOut[b] = best;
        if (pathOut) {
            int tag = bt;
            pathOut[(size_t)b * 512 + 511] = (float)tag;
            for (int t = 511; t >= 1; t--) {
                tag = bp[t][tag];
                pathOut[(size_t)b * 512 + (t - 1)] = (float)tag;
            }
        }
    }
}

// ---------------------------------------------------------------------------
extern "C" void kernel_launch(void* const* d_in, const int* in_sizes, int n_in,
                              void* d_out, int out_size)
{
    const int*   sent  = (const int*)d_in[0];
    // d_in[1] = batch_lengths (all == T; unused)
    const float* emb   = (const float*)d_in[2];
    const float* fcw   = (const float*)d_in[3];
    const float* fcb   = (const float*)d_in[4];
    const float* trans = (const float*)d_in[5];
    const float* wih0f = (const float*)d_in[6];
    const float* whh0f = (const float*)d_in[7];
    const float* b0f   = (const float*)d_in[8];
    const float* wih0b = (const float*)d_in[9];
    const float* whh0b = (const float*)d_in[10];
    const float* b0b   = (const float*)d_in[11];
    const float* wih1f = (const float*)d_in[12];
    const float* whh1f = (const float*)d_in[13];
    const float* b1f   = (const float*)d_in[14];
    const float* wih1b = (const float*)d_in[15];
    const float* whh1b = (const float*)d_in[16];
    const float* b1b   = (const float*)d_in[17];
    float* out = (float*)d_out;

    int mode = 0;
    if (out_size == 64 * 512) mode = 1;         // path only
    else if (out_size == 64) mode = 2;          // score only
    // default: [score(64) | path(64*512)]

    dim3 pgrid(16, 256);
    proj_kernel<<<pgrid, 256>>>(sent, emb, wih0f, b0f, wih0b, b0b, 300, 0);
    rec_kernel<<<128, 256>>>(whh0f, whh0b, 0);
    proj_kernel<<<pgrid, 256>>>(sent, emb, wih1f, b1f, wih1b, b1b, 512, 1);
    rec_kernel<<<128, 256>>>(whh1f, whh1b, 1);
    feats_kernel<<<4096, 256>>>(fcw, fcb);
    viterbi_kernel<<<64, 32>>>(trans, out, mode);
}